// round 14
// baseline (speedup 1.0000x reference)
#include <cuda_runtime.h>
#include <cuda_bf16.h>
#include <cstdint>

#define BB 2
#define SS 2048
#define HH 1024
#define NH 16
#define HD 64
#define MM (BB*SS)   // 4096 rows

// Scratch (allocation is forbidden; use __device__ globals)
__device__ uint32_t g_xTF[(size_t)MM*HH];         // x as tf32
__device__ uint32_t g_xHL[(size_t)MM*HH];         // x as bf16 hi/lo pair-interleaved
__device__ uint32_t g_WdHL[(size_t)(HH/2)*2*HH];  // Wq-Wk, bf16 hi/lo: [512 k-pairs][2048]
__device__ uint32_t g_WvTF[(size_t)HH*HH];        // Wv as tf32
__device__ uint32_t g_WoTF[(size_t)HH*HH];        // Wo as tf32
__device__ float    g_bd[HH];
__device__ uint32_t g_DHL[(size_t)MM*HH];         // D, bf16 hi/lo, quad-permuted per head
__device__ uint32_t g_VtP[(size_t)BB*NH*HD*SS];   // V^T tf32, keys in PHI order, per (b,h)
__device__ uint32_t g_C[(size_t)MM*HH];           // ctx as tf32

__device__ __forceinline__ uint32_t f2tf32(float x) {
    uint32_t r;
    asm("cvt.rna.tf32.f32 %0, %1;" : "=r"(r) : "f"(x));
    return r;
}
__device__ __forceinline__ uint32_t bfpack(float x0, float x1) {
    __nv_bfloat162 t;
    t.x = __float2bfloat16_rn(x0);
    t.y = __float2bfloat16_rn(x1);
    return *(uint32_t*)&t;
}
__device__ __forceinline__ void bfsplit2(float x0, float x1, uint32_t& hi, uint32_t& lo) {
    __nv_bfloat16 h0 = __float2bfloat16_rn(x0), h1 = __float2bfloat16_rn(x1);
    float r0 = x0 - __bfloat162float(h0), r1 = x1 - __bfloat162float(h1);
    __nv_bfloat162 th; th.x = h0; th.y = h1;
    hi = *(uint32_t*)&th;
    lo = bfpack(r0, r1);
}
__device__ __forceinline__ void mma8(float* c,
                                     uint32_t a0, uint32_t a1, uint32_t a2, uint32_t a3,
                                     uint32_t b0, uint32_t b1) {
    asm volatile(
        "mma.sync.aligned.m16n8k8.row.col.f32.tf32.tf32.f32 "
        "{%0,%1,%2,%3}, {%4,%5,%6,%7}, {%8,%9}, {%0,%1,%2,%3};"
        : "+f"(c[0]), "+f"(c[1]), "+f"(c[2]), "+f"(c[3])
        : "r"(a0), "r"(a1), "r"(a2), "r"(a3), "r"(b0), "r"(b1));
}
__device__ __forceinline__ void mma16(float* c,
                                      uint32_t a0, uint32_t a1, uint32_t a2, uint32_t a3,
                                      uint32_t b0, uint32_t b1) {
    asm volatile(
        "mma.sync.aligned.m16n8k16.row.col.f32.bf16.bf16.f32 "
        "{%0,%1,%2,%3}, {%4,%5,%6,%7}, {%8,%9}, {%0,%1,%2,%3};"
        : "+f"(c[0]), "+f"(c[1]), "+f"(c[2]), "+f"(c[3])
        : "r"(a0), "r"(a1), "r"(a2), "r"(a3), "r"(b0), "r"(b1));
}
__device__ __forceinline__ uint32_t smem_u32(const void* p) {
    uint32_t a;
    asm("{ .reg .u64 t; cvta.to.shared.u64 t, %1; cvt.u32.u64 %0, t; }" : "=r"(a) : "l"(p));
    return a;
}
__device__ __forceinline__ void cp16(uint32_t dst, const void* src) {
    asm volatile("cp.async.ca.shared.global [%0], [%1], 16;" :: "r"(dst), "l"(src));
}
__device__ __forceinline__ void cp_commit() { asm volatile("cp.async.commit_group;"); }
template<int N> __device__ __forceinline__ void cp_wait() {
    asm volatile("cp.async.wait_group %0;" :: "n"(N));
}

// ---------------------------------------------------------------------------
// Prep kernels
// ---------------------------------------------------------------------------
__global__ void prep_x(const float* __restrict__ x) {
    int i = blockIdx.x * blockDim.x + threadIdx.x;   // over MM*HH/4
    float4 v = ((const float4*)x)[i];
    ((uint4*)g_xTF)[i] = make_uint4(f2tf32(v.x), f2tf32(v.y), f2tf32(v.z), f2tf32(v.w));
    uint32_t h0, l0, h1, l1;
    bfsplit2(v.x, v.y, h0, l0);
    bfsplit2(v.z, v.w, h1, l1);
    ((uint4*)g_xHL)[i] = make_uint4(h0, l0, h1, l1);
}
__global__ void prep_wd(const float* __restrict__ Wq, const float* __restrict__ Wk,
                        const float* __restrict__ bq, const float* __restrict__ bk) {
    int i = blockIdx.x * blockDim.x + threadIdx.x;   // over 512*1024
    int p = i >> 10, n = i & 1023;
    float a0 = Wq[(size_t)(2*p)   * HH + n] - Wk[(size_t)(2*p)   * HH + n];
    float a1 = Wq[(size_t)(2*p+1) * HH + n] - Wk[(size_t)(2*p+1) * HH + n];
    uint32_t h, l; bfsplit2(a0, a1, h, l);
    *(uint2*)&g_WdHL[(size_t)p * 2048 + 2*n] = make_uint2(h, l);
    if (i < HH) g_bd[i] = bq[i] - bk[i];
}
__global__ void prep_tf2(const float* __restrict__ s0, uint32_t* __restrict__ d0,
                         const float* __restrict__ s1, uint32_t* __restrict__ d1) {
    int i = blockIdx.x * blockDim.x + threadIdx.x;   // over HH*HH/4
    const float* src = blockIdx.y ? s1 : s0;
    uint32_t* dst = blockIdx.y ? d1 : d0;
    float4 v = ((const float4*)src)[i];
    ((uint4*)dst)[i] = make_uint4(f2tf32(v.x), f2tf32(v.y), f2tf32(v.z), f2tf32(v.w));
}

// ---------------------------------------------------------------------------
// tf32 GEMM, cp.async double-buffered. R11-proven (256 thr, 64x32 warp tiles,
// reg-capped for 2 CTAs/SM).
// MODE 0: fp32 out (final). MODE 3: V out -> g_VtP transposed, PHI keys.
// ---------------------------------------------------------------------------
template<int MODE>
__global__ __launch_bounds__(256, 2) void gemm_tc(const uint32_t* __restrict__ A,
                                                  const uint32_t* __restrict__ W,
                                                  const float* __restrict__ bias,
                                                  void* __restrict__ Cout) {
    const int ASZ = 128 * 20, BSZ = 16 * 136;
    __shared__ uint32_t As[2 * ASZ];
    __shared__ uint32_t Bs[2 * BSZ];
    int tid = threadIdx.x, lane = tid & 31, w = tid >> 5;
    int la3 = lane & 3, l4 = lane >> 2;
    int wm = (w & 1) * 64, wn = (w >> 1) * 32;
    int row0 = blockIdx.y * 128, col0 = blockIdx.x * 128;

    uint32_t asb = smem_u32(As), bsb = smem_u32(Bs);
    float acc[4][4][4] = {};

    #define G_FILL(T) do {                                                       \
        int k0 = (T) * 16, bf = (T) & 1;                                         \
        _Pragma("unroll")                                                        \
        for (int i = 0; i < 2; i++) {                                            \
            int f = tid + i * 256;                                               \
            int r = f >> 2, j = f & 3;                                           \
            cp16(asb + (bf * ASZ + r * 20 + 4 * j) * 4,                          \
                 A + (size_t)(row0 + r) * HH + k0 + 4 * j);                      \
        }                                                                        \
        _Pragma("unroll")                                                        \
        for (int i = 0; i < 2; i++) {                                            \
            int f = tid + i * 256;                                               \
            int r = f >> 5, j = f & 31;                                          \
            cp16(bsb + (bf * BSZ + r * 136 + 4 * j) * 4,                         \
                 W + (size_t)(k0 + r) * HH + col0 + 4 * j);                      \
        }                                                                        \
    } while (0)

    G_FILL(0); cp_commit();

    for (int t = 0; t < HH / 16; t++) {
        if (t + 1 < HH / 16) { G_FILL(t + 1); cp_commit(); cp_wait<1>(); }
        else                 { cp_wait<0>(); }
        __syncthreads();
        const uint32_t* Ab = As + (t & 1) * ASZ;
        const uint32_t* Bb = Bs + (t & 1) * BSZ;

        #pragma unroll
        for (int kk = 0; kk < 16; kk += 8) {
            int rc = (kk + la3) * 136, rd = (kk + 4 + la3) * 136;
            uint32_t bf[4][2];
            #pragma unroll
            for (int nt = 0; nt < 4; nt++) {
                int n = wn + nt * 8 + l4;
                bf[nt][0] = Bb[rc + n];
                bf[nt][1] = Bb[rd + n];
            }
            #pragma unroll
            for (int mt = 0; mt < 4; mt++) {
                int m = wm + mt * 16 + l4;
                uint32_t a0 = Ab[m * 20 + kk + la3];
                uint32_t a1 = Ab[(m + 8) * 20 + kk + la3];
                uint32_t a2 = Ab[m * 20 + kk + 4 + la3];
                uint32_t a3 = Ab[(m + 8) * 20 + kk + 4 + la3];
                #pragma unroll
                for (int nt = 0; nt < 4; nt++)
                    mma8(acc[mt][nt], a0, a1, a2, a3, bf[nt][0], bf[nt][1]);
            }
        }
        __syncthreads();
    }
    #undef G_FILL

    #pragma unroll
    for (int mt = 0; mt < 4; mt++) {
        int r = row0 + wm + mt * 16 + l4;
        #pragma unroll
        for (int nt = 0; nt < 4; nt++) {
            int cb = col0 + wn + nt * 8 + 2 * la3;
            float v0 = acc[mt][nt][0] + bias[cb];
            float v1 = acc[mt][nt][1] + bias[cb + 1];
            float v2 = acc[mt][nt][2] + bias[cb];
            float v3 = acc[mt][nt][3] + bias[cb + 1];
            if (MODE == 0) {
                float* C = (float*)Cout;
                C[(size_t)r       * HH + cb    ] = v0;
                C[(size_t)r       * HH + cb + 1] = v1;
                C[(size_t)(r + 8) * HH + cb    ] = v2;
                C[(size_t)(r + 8) * HH + cb + 1] = v3;
            } else {
                // V: transposed, keys PHI-permuted (r&15 = l4 < 8, so PHI(r+8)=PHI(r)+2)
                uint32_t* VtP = (uint32_t*)Cout;
                int bI = r >> 11, s = r & 2047;
                int hI = cb >> 6, d = cb & 63;
                int pos = 16 * (s >> 4) + 4 * ((s >> 1) & 3) + 2 * ((s >> 3) & 1) + (s & 1);
                size_t hb = (size_t)(bI * NH + hI) * HD;
                VtP[(hb + d)     * SS + pos    ] = f2tf32(v0);
                VtP[(hb + d + 1) * SS + pos    ] = f2tf32(v1);
                VtP[(hb + d)     * SS + pos + 2] = f2tf32(v2);
                VtP[(hb + d + 1) * SS + pos + 2] = f2tf32(v3);
            }
        }
    }
}

// ---------------------------------------------------------------------------
// D = x @ Wd + bd in 3xBF16 (m16n8k16), cp.async double-buffered.
// R11-proven (256 thr, 64x32 warp tiles, reg-capped). Quad-permuted output.
// ---------------------------------------------------------------------------
__global__ __launch_bounds__(256, 2) void gemm_bf3(const uint32_t* __restrict__ AHL,
                                                   const uint32_t* __restrict__ WHL,
                                                   const float* __restrict__ bias,
                                                   uint32_t* __restrict__ Dout) {
    extern __shared__ uint32_t sm[];
    const int ASZ = 128 * 40, BSZ = 16 * 264;
    uint32_t* Asm = sm;
    uint32_t* Bsm = sm + 2 * ASZ;
    int tid = threadIdx.x, lane = tid & 31, w = tid >> 5;
    int la3 = lane & 3, l4 = lane >> 2;
    int wm = (w & 1) * 64, wn = (w >> 1) * 32;
    int row0 = blockIdx.y * 128, col0 = blockIdx.x * 128;

    uint32_t asb = smem_u32(Asm), bsb = smem_u32(Bsm);
    float acc[4][4][4] = {};

    #define B_FILL(T) do {                                                       \
        int u0 = (T) * 32, p0 = (T) * 16, bf = (T) & 1;                          \
        _Pragma("unroll")                                                        \
        for (int i = 0; i < 4; i++) {                                            \
            int f = tid + i * 256;                                               \
            int r = f >> 3, j = f & 7;                                           \
            cp16(asb + (bf * ASZ + r * 40 + 4 * j) * 4,                          \
                 AHL + (size_t)(row0 + r) * HH + u0 + 4 * j);                    \
        }                                                                        \
        _Pragma("unroll")                                                        \
        for (int i = 0; i < 4; i++) {                                            \
            int f = tid + i * 256;                                               \
            int p = f >> 6, j = f & 63;                                          \
            cp16(bsb + (bf * BSZ + p * 264 + 4 * j) * 4,                         \
                 WHL + (size_t)(p0 + p) * 2048 + 2 * col0 + 4 * j);              \
        }                                                                        \
    } while (0)

    B_FILL(0); cp_commit();

    for (int t = 0; t < HH / 32; t++) {
        if (t + 1 < HH / 32) { B_FILL(t + 1); cp_commit(); cp_wait<1>(); }
        else                 { cp_wait<0>(); }
        __syncthreads();
        const uint32_t* Ab = Asm + (t & 1) * ASZ;
        const uint32_t* Bb = Bsm + (t & 1) * BSZ;

        #pragma unroll
        for (int K = 0; K < 2; K++) {
            int pb = K * 8;
            uint2 Bf0[4], Bf1[4];
            #pragma unroll
            for (int nt = 0; nt < 4; nt++) {
                int n = wn + nt * 8 + l4;
                Bf0[nt] = *(const uint2*)&Bb[(pb + la3)     * 264 + 2 * n];
                Bf1[nt] = *(const uint2*)&Bb[(pb + 4 + la3) * 264 + 2 * n];
            }
            #pragma unroll
            for (int mt = 0; mt < 4; mt++) {
                int m = wm + mt * 16 + l4;
                uint2 A0 = *(const uint2*)&Ab[m       * 40 + 2 * (pb + la3)];
                uint2 A1 = *(const uint2*)&Ab[(m + 8) * 40 + 2 * (pb + la3)];
                uint2 A2 = *(const uint2*)&Ab[m       * 40 + 2 * (pb + 4 + la3)];
                uint2 A3 = *(const uint2*)&Ab[(m + 8) * 40 + 2 * (pb + 4 + la3)];
                #pragma unroll
                for (int nt = 0; nt < 4; nt++) {
                    mma16(acc[mt][nt], A0.x, A1.x, A2.x, A3.x, Bf0[nt].x, Bf1[nt].x);
                    mma16(acc[mt][nt], A0.x, A1.x, A2.x, A3.x, Bf0[nt].y, Bf1[nt].y);
                    mma16(acc[mt][nt], A0.y, A1.y, A2.y, A3.y, Bf0[nt].x, Bf1[nt].x);
                }
            }
        }
        __syncthreads();
    }
    #undef B_FILL

    #pragma unroll
    for (int mt = 0; mt < 4; mt++) {
        int r = row0 + wm + mt * 16 + l4;
        #pragma unroll
        for (int nt = 0; nt < 4; nt++) {
            int cb = col0 + wn + nt * 8 + 2 * la3;
            int p = cb >> 1;                 // global dim-pair index
            int head = p >> 5, q = p & 31;
            int off = head * 64 + 16 * (q >> 3) + 4 * (q & 3) + 2 * ((q >> 2) & 1);
            float v0 = acc[mt][nt][0] + bias[cb];
            float v1 = acc[mt][nt][1] + bias[cb + 1];
            float v2 = acc[mt][nt][2] + bias[cb];
            float v3 = acc[mt][nt][3] + bias[cb + 1];
            uint32_t h, l;
            bfsplit2(v0, v1, h, l);
            *(uint2*)&Dout[(size_t)r * HH + off] = make_uint2(h, l);
            bfsplit2(v2, v3, h, l);
            *(uint2*)&Dout[(size_t)(r + 8) * HH + off] = make_uint2(h, l);
        }
    }
}

// ---------------------------------------------------------------------------
// Fused anti-causal gaussian attention. QK 3xBF16, PV tf32.
// Q-tile 128 rows (256 threads, 8 warps of 16 q-rows each), K-tile 64:
// halves fill+sync events per mma vs R11. Per-warp state unchanged.
// Smem: Dk[64][64] + Vp[64][64] + Ps[128][64] = 64KB -> 2 CTAs/SM.
// Grid (h, b, qb) with qb slowest (LPT).
// ---------------------------------------------------------------------------
__global__ __launch_bounds__(256, 2) void attn_tc(const uint32_t* __restrict__ DH,
                                                  const uint32_t* __restrict__ VtP,
                                                  uint32_t* __restrict__ C) {
    extern __shared__ uint32_t sm[];
    const int DK0 = 0;                 // [64][64] bf16 pairs, quad-permuted
    const int VT0 = 64 * 64;           // [64][64] tf32, PHI keys
    const int PS0 = 2 * 64 * 64;       // [128][64] tf32, PHI keys

    int tid = threadIdx.x, lane = tid & 31, w = tid >> 5;
    int la3 = lane & 3, l4 = lane >> 2;
    int h = blockIdx.x, b = blockIdx.y, q0 = blockIdx.z * 128;
    const uint32_t* DHb = DH + (size_t)b * SS * HH + h * 64;
    const uint32_t* Vb  = VtP + (size_t)(b * NH + h) * HD * SS;
    int qrow = w * 16 + l4;            // 0..127
    int sw = (l4 & 1) << 4;

    uint32_t smb = smem_u32(sm);
    uint32_t dkb = smb + DK0 * 4;
    uint32_t vtb = smb + VT0 * 4;

    // Q-side fragments: one uint4 per (K, rowhalf) — quad-permuted gmem layout
    uint32_t aH[4][4], aL[4][4];
    {
        const uint32_t* r0 = DHb + (size_t)(q0 + qrow) * HH;
        const uint32_t* r8 = r0 + (size_t)8 * HH;
        #pragma unroll
        for (int K = 0; K < 4; K++) {
            uint4 Q0 = *(const uint4*)&r0[16 * K + 4 * la3];
            uint4 Q8 = *(const uint4*)&r8[16 * K + 4 * la3];
            aH[K][0] = Q0.x; aL[K][0] = Q0.y; aH[K][2] = Q0.z; aL[K][2] = Q0.w;
            aH[K][1] = Q8.x; aL[K][1] = Q8.y; aH[K][3] = Q8.z; aL[K][3] = Q8.w;
        }
    }

    float ctx[8][4] = {};
    int nT = (SS - q0) / 64;

    // Dk fill: 64 rows x 64 u32 = 1024 cp16 over 256 threads = 4/thread
    #define FILL_DK(T) do {                                                      \
        int k0t = q0 + (T) * 64;                                                 \
        _Pragma("unroll")                                                        \
        for (int i = 0; i < 4; i++) {                                            \
            int idx = tid + i * 256;                                             \
            int r = idx >> 4, j = idx & 15;                                      \
            cp16(dkb + (r * 64 + ((4 * j) ^ ((r & 1) << 4))) * 4,                \
                 DHb + (size_t)(k0t + r) * HH + 4 * j);                          \
        }                                                                        \
    } while (0)
    #define FILL_V(T) do {                                                       \
        int k0t = q0 + (T) * 64;                                                 \
        _Pragma("unroll")                                                        \
        for (int i = 0; i < 4; i++) {                                            \
            int idx = tid + i * 256;                                             \
            int d = idx >> 4, j = idx & 15;                                      \
            cp16(vtb + (d * 64 + ((4 * j) ^ ((d & 1) << 4))) * 4,                \
                 Vb + (size_t)d * SS + k0t + 4 * j);                             \
        }                                                                        \
    } while (0)

    FILL_DK(0); cp_commit();
    FILL_V(0);  cp_commit();

    for (int t = 0; t < nT; t++) {
        int k0 = q0 + t * 64;
        cp_wait<1>();          // Dk(t) resident
        __syncthreads();

        const uint32_t* Dk = sm + DK0;
        const uint32_t* Vp = sm + VT0;
        uint32_t* Pw = sm + PS0;

        // ---- QK: S[16q x 64k] per warp, 3xBF16 over d=64 (all LDS.128) ----
        float s4[8][4] = {};
        #pragma unroll
        for (int K = 0; K < 4; K++) {
            #pragma unroll
            for (int nt = 0; nt < 8; nt++) {
                const uint32_t* br = Dk + (nt * 8 + l4) * 64;
                uint4 Dq = *(const uint4*)&br[(16 * K + 4 * la3) ^ sw];
                mma16(s4[nt], aH[K][0], aH[K][1], aH[K][2], aH[K][3], Dq.x, Dq.z);
                mma16(s4[nt], aH[K][0], aH[K][1], aH[K][2], aH[K][3], Dq.y, Dq.w);
                mma16(s4[nt], aL[K][0], aL[K][1], aL[K][2], aL[K][3], Dq.x, Dq.z);
            }
        }

        __syncthreads();                       // all warps done reading Dk
        if (t + 1 < nT) FILL_DK(t + 1);        // overlaps mask + PV
        cp_commit();

        // ---- mask (k > q strictly) + exp -> Ps (PHI layout, STS.128) ----
        #pragma unroll
        for (int kt2 = 0; kt2 < 4; kt2++) {
            int nt0 = 2 * kt2, nt1 = nt0 + 1;
            int kg0 = k0 + nt0 * 8 + 2 * la3;
            int kg1 = k0 + nt1 * 8 + 2 * la3;
            int qa = q0 + qrow, qb8 = qa + 8;
            float e0 = (kg0     > qa) ? __expf(-0.5f * s4[nt0][0]) : 0.0f;
            float e1 = (kg0 + 1 > qa) ? __expf(-0.5f * s4[nt0][1]) : 0.0f;
            float e2 = (kg1     > qa) ? __expf(-0.5f * s4[nt1][0]) : 0.0f;
            float e3 = (kg1 + 1 > qa) ? __expf(-0.5f * s4[nt1][1]) : 0.0f;
            *(uint4*)&Pw[qrow * 64 + ((16 * kt2 + 4 * la3) ^ sw)] =
                make_uint4(f2tf32(e0), f2tf32(e1), f2tf32(e2), f2tf32(e3));
            e0 = (kg0     > qb8) ? __expf(-0.5f * s4[nt0][2]) : 0.0f;
            e1 = (kg0 + 1 > qb8) ? __expf(-0.5f * s4[nt0][3]) : 0.0f;
            e2 = (kg1     > qb8) ? __expf(-0.5f * s4[nt1][2]) : 0.0f;
            e3 = (kg1 + 1 > qb8) ? __expf(-0.5f * s4[nt1][3]) : 0.0f;
            *(uint4*)&Pw[(qrow + 8) * 64 + ((16 * kt2 + 4 * la3) ^ sw)] =
                make_uint4(f2tf32(e0), f2tf32(e1), f2tf32(e2), f2tf32(e3));
        }
        __syncwarp();   // Pw rows are warp-private

        cp_wait<1>();          // V(t) resident
        __syncthreads();

        // ---- PV: ctx += P @ V over 64 keys (all LDS.128) ----
        #pragma unroll
        for (int kt2 = 0; kt2 < 4; kt2++) {
            uint4 Pa = *(const uint4*)&Pw[qrow * 64 + ((16 * kt2 + 4 * la3) ^ sw)];
            uint4 Pb = *(const uint4*)&Pw[(qrow + 8) * 64 + ((16 * kt2 + 4 * la3) ^ sw)];
            #pragma unroll
            for (int nt = 0; nt < 8; nt++) {
                int vr = nt * 8 + l4;
                uint4 Vq = *(const uint4*)&Vp[vr * 64 + ((16 * kt2 + 4 * la3) ^ ((vr & 1) << 4))];
                mma8(ctx[nt], Pa.x, Pb.x, Pa.y, Pb.y, Vq.x, Vq.y);
                mma8(ctx[nt], Pa.z, Pb.z, Pa.w, Pb.w, Vq.z, Vq.w);
            }
        }

        __syncthreads();                       // all warps done reading Vp/Ps
        if (t + 1 < nT) FILL_V(t + 1);         // overlaps next QK
        cp_commit();
    }

    // Store ctx as tf32 in merged [B,S,H] layout
    uint32_t* Cb = C + (size_t)b * SS * HH + h * HD;
    #pragma unroll
    for (int nt = 0; nt < 8; nt++) {
        int r = q0 + qrow;
        int c = nt * 8 + 2 * la3;
        *(uint2*)&Cb[(size_t)r       * HH + c] = make_uint2(f2tf32(ctx[nt][0]), f2tf32(ctx[nt][1]));
        *(uint2*)&Cb[(size_t)(r + 8) * HH + c] = make_uint2(f2tf32(ctx[nt][2]), f2tf32(ctx[nt][3]));
    }
    #undef FILL_DK
    #undef FILL_V
}

static const int ATTN_SMEM = (4 * 64 * 64) * 4;                  // 65536 B
static const int BF3_SMEM  = (2 * 128 * 40 + 2 * 16 * 264) * 4;  // 74752 B

extern "C" void kernel_launch(void* const* d_in, const int* in_sizes, int n_in,
                              void* d_out, int out_size) {
    const float* x  = (const float*)d_in[0];
    const float* Wq = (const float*)d_in[1];
    const float* bq = (const float*)d_in[2];
    const float* Wk = (const float*)d_in[3];
    const float* bk = (const float*)d_in[4];
    const float* Wv = (const float*)d_in[5];
    const float* bv = (const float*)d_in[6];
    const float* Wo = (const float*)d_in[7];
    const float* bo = (const float*)d_in[8];
    float* out = (float*)d_out;

    uint32_t *pxTF, *pxHL, *pWdHL, *pWvTF, *pWoTF, *pDHL, *pVtP, *pC;
    float *pbd;
    cudaGetSymbolAddress((void**)&pxTF,  g_xTF);
    cudaGetSymbolAddress((void**)&pxHL,  g_xHL);
    cudaGetSymbolAddress((void**)&pWdHL, g_WdHL);
    cudaGetSymbolAddress((void**)&pWvTF, g_WvTF);
    cudaGetSymbolAddress((void**)&pWoTF, g_WoTF);
    cudaGetSymbolAddress((void**)&pbd,   g_bd);
    cudaGetSymbolAddress((void**)&pDHL,  g_DHL);
    cudaGetSymbolAddress((void**)&pVtP,  g_VtP);
    cudaGetSymbolAddress((void**)&pC,    g_C);

    static bool attr_set = false;
    if (!attr_set) {
        cudaFuncSetAttribute(attn_tc, cudaFuncAttributeMaxDynamicSharedMemorySize, ATTN_SMEM);
        cudaFuncSetAttribute(gemm_bf3, cudaFuncAttributeMaxDynamicSharedMemorySize, BF3_SMEM);
        attr_set = true;
    }

    // 1. prep
    prep_x  <<<(MM * HH / 4) / 256, 256>>>(x);
    prep_wd <<<(512 * 1024) / 256, 256>>>(Wq, Wk, bq, bk);
    prep_tf2<<<dim3((HH * HH / 4) / 256, 2), 256>>>(Wv, pWvTF, Wo, pWoTF);

    // 2. D = x @ Wd + bd (3xBF16) ; V = x @ Wv + bv (tf32, direct PHI VtP out)
    dim3 ggrid(HH / 128, MM / 128);
    gemm_bf3<<<ggrid, 256, BF3_SMEM>>>(pxHL, pWdHL, pbd, pDHL);
    gemm_tc<3><<<ggrid, 256>>>(pxTF, pWvTF, bv, pVtP);

    // 3. fused attention (Q-tile 128; LPT: qb slowest-varying)
    dim3 agrid(NH, BB, SS / 128);
    attn_tc<<<agrid, 256, ATTN_SMEM>>>(pDHL, pVtP, pC);

    // 4. out = ctx @ Wo + bo (tf32)
    gemm_tc<0><<<ggrid, 256>>>(pC, pWoTF, bo, out);
}

// round 15
// speedup vs baseline: 1.5827x; 1.5827x over previous
#include <cuda_runtime.h>
#include <cuda_bf16.h>
#include <cstdint>

#define BB 2
#define SS 2048
#define HH 1024
#define NH 16
#define HD 64
#define MM (BB*SS)   // 4096 rows

// Scratch (allocation is forbidden; use __device__ globals)
__device__ uint32_t g_xTF[(size_t)MM*HH];         // x as tf32
__device__ uint32_t g_xHL[(size_t)MM*HH];         // x as bf16 hi/lo pair-interleaved
__device__ uint32_t g_WdHL[(size_t)(HH/2)*2*HH];  // Wq-Wk, bf16 hi/lo: [512 k-pairs][2048]
__device__ uint32_t g_WvTF[(size_t)HH*HH];        // Wv as tf32
__device__ uint32_t g_WoTF[(size_t)HH*HH];        // Wo as tf32
__device__ float    g_bd[HH];
__device__ uint32_t g_DHL[(size_t)MM*HH];         // D, bf16 hi/lo, quad-permuted per head
__device__ uint32_t g_VtP[(size_t)BB*NH*HD*SS];   // V^T tf32, keys in PHI order, per (b,h)
__device__ uint32_t g_C[(size_t)MM*HH];           // ctx as tf32

__device__ __forceinline__ uint32_t f2tf32(float x) {
    uint32_t r;
    asm("cvt.rna.tf32.f32 %0, %1;" : "=r"(r) : "f"(x));
    return r;
}
__device__ __forceinline__ uint32_t bfpack(float x0, float x1) {
    __nv_bfloat162 t;
    t.x = __float2bfloat16_rn(x0);
    t.y = __float2bfloat16_rn(x1);
    return *(uint32_t*)&t;
}
__device__ __forceinline__ void bfsplit2(float x0, float x1, uint32_t& hi, uint32_t& lo) {
    __nv_bfloat16 h0 = __float2bfloat16_rn(x0), h1 = __float2bfloat16_rn(x1);
    float r0 = x0 - __bfloat162float(h0), r1 = x1 - __bfloat162float(h1);
    __nv_bfloat162 th; th.x = h0; th.y = h1;
    hi = *(uint32_t*)&th;
    lo = bfpack(r0, r1);
}
__device__ __forceinline__ void mma8(float* c,
                                     uint32_t a0, uint32_t a1, uint32_t a2, uint32_t a3,
                                     uint32_t b0, uint32_t b1) {
    asm volatile(
        "mma.sync.aligned.m16n8k8.row.col.f32.tf32.tf32.f32 "
        "{%0,%1,%2,%3}, {%4,%5,%6,%7}, {%8,%9}, {%0,%1,%2,%3};"
        : "+f"(c[0]), "+f"(c[1]), "+f"(c[2]), "+f"(c[3])
        : "r"(a0), "r"(a1), "r"(a2), "r"(a3), "r"(b0), "r"(b1));
}
__device__ __forceinline__ void mma16(float* c,
                                      uint32_t a0, uint32_t a1, uint32_t a2, uint32_t a3,
                                      uint32_t b0, uint32_t b1) {
    asm volatile(
        "mma.sync.aligned.m16n8k16.row.col.f32.bf16.bf16.f32 "
        "{%0,%1,%2,%3}, {%4,%5,%6,%7}, {%8,%9}, {%0,%1,%2,%3};"
        : "+f"(c[0]), "+f"(c[1]), "+f"(c[2]), "+f"(c[3])
        : "r"(a0), "r"(a1), "r"(a2), "r"(a3), "r"(b0), "r"(b1));
}
__device__ __forceinline__ uint32_t smem_u32(const void* p) {
    uint32_t a;
    asm("{ .reg .u64 t; cvta.to.shared.u64 t, %1; cvt.u32.u64 %0, t; }" : "=r"(a) : "l"(p));
    return a;
}
__device__ __forceinline__ void cp16(uint32_t dst, const void* src) {
    asm volatile("cp.async.ca.shared.global [%0], [%1], 16;" :: "r"(dst), "l"(src));
}
__device__ __forceinline__ void cp_commit() { asm volatile("cp.async.commit_group;"); }
template<int N> __device__ __forceinline__ void cp_wait() {
    asm volatile("cp.async.wait_group %0;" :: "n"(N));
}

// ---------------------------------------------------------------------------
// Prep kernels
// ---------------------------------------------------------------------------
__global__ void prep_x(const float* __restrict__ x) {
    int i = blockIdx.x * blockDim.x + threadIdx.x;   // over MM*HH/4
    float4 v = ((const float4*)x)[i];
    ((uint4*)g_xTF)[i] = make_uint4(f2tf32(v.x), f2tf32(v.y), f2tf32(v.z), f2tf32(v.w));
    uint32_t h0, l0, h1, l1;
    bfsplit2(v.x, v.y, h0, l0);
    bfsplit2(v.z, v.w, h1, l1);
    ((uint4*)g_xHL)[i] = make_uint4(h0, l0, h1, l1);
}
__global__ void prep_wd(const float* __restrict__ Wq, const float* __restrict__ Wk,
                        const float* __restrict__ bq, const float* __restrict__ bk) {
    int i = blockIdx.x * blockDim.x + threadIdx.x;   // over 512*1024
    int p = i >> 10, n = i & 1023;
    float a0 = Wq[(size_t)(2*p)   * HH + n] - Wk[(size_t)(2*p)   * HH + n];
    float a1 = Wq[(size_t)(2*p+1) * HH + n] - Wk[(size_t)(2*p+1) * HH + n];
    uint32_t h, l; bfsplit2(a0, a1, h, l);
    *(uint2*)&g_WdHL[(size_t)p * 2048 + 2*n] = make_uint2(h, l);
    if (i < HH) g_bd[i] = bq[i] - bk[i];
}
__global__ void prep_tf2(const float* __restrict__ s0, uint32_t* __restrict__ d0,
                         const float* __restrict__ s1, uint32_t* __restrict__ d1) {
    int i = blockIdx.x * blockDim.x + threadIdx.x;   // over HH*HH/4
    const float* src = blockIdx.y ? s1 : s0;
    uint32_t* dst = blockIdx.y ? d1 : d0;
    float4 v = ((const float4*)src)[i];
    ((uint4*)dst)[i] = make_uint4(f2tf32(v.x), f2tf32(v.y), f2tf32(v.z), f2tf32(v.w));
}

// ---------------------------------------------------------------------------
// tf32 GEMM, cp.async double-buffered. 256 thr, 64x32 warp tiles,
// reg-capped for 2 CTAs/SM (single wave + 4 warps/SMSP).
// MODE 0: fp32 out (final). MODE 3: V out -> g_VtP transposed, PHI keys.
// ---------------------------------------------------------------------------
template<int MODE>
__global__ __launch_bounds__(256, 2) void gemm_tc(const uint32_t* __restrict__ A,
                                                  const uint32_t* __restrict__ W,
                                                  const float* __restrict__ bias,
                                                  void* __restrict__ Cout) {
    const int ASZ = 128 * 20, BSZ = 16 * 136;
    __shared__ uint32_t As[2 * ASZ];
    __shared__ uint32_t Bs[2 * BSZ];
    int tid = threadIdx.x, lane = tid & 31, w = tid >> 5;
    int la3 = lane & 3, l4 = lane >> 2;
    int wm = (w & 1) * 64, wn = (w >> 1) * 32;
    int row0 = blockIdx.y * 128, col0 = blockIdx.x * 128;

    uint32_t asb = smem_u32(As), bsb = smem_u32(Bs);
    float acc[4][4][4] = {};

    #define G_FILL(T) do {                                                       \
        int k0 = (T) * 16, bf = (T) & 1;                                         \
        _Pragma("unroll")                                                        \
        for (int i = 0; i < 2; i++) {                                            \
            int f = tid + i * 256;                                               \
            int r = f >> 2, j = f & 3;                                           \
            cp16(asb + (bf * ASZ + r * 20 + 4 * j) * 4,                          \
                 A + (size_t)(row0 + r) * HH + k0 + 4 * j);                      \
        }                                                                        \
        _Pragma("unroll")                                                        \
        for (int i = 0; i < 2; i++) {                                            \
            int f = tid + i * 256;                                               \
            int r = f >> 5, j = f & 31;                                          \
            cp16(bsb + (bf * BSZ + r * 136 + 4 * j) * 4,                         \
                 W + (size_t)(k0 + r) * HH + col0 + 4 * j);                      \
        }                                                                        \
    } while (0)

    G_FILL(0); cp_commit();

    for (int t = 0; t < HH / 16; t++) {
        if (t + 1 < HH / 16) { G_FILL(t + 1); cp_commit(); cp_wait<1>(); }
        else                 { cp_wait<0>(); }
        __syncthreads();
        const uint32_t* Ab = As + (t & 1) * ASZ;
        const uint32_t* Bb = Bs + (t & 1) * BSZ;

        #pragma unroll
        for (int kk = 0; kk < 16; kk += 8) {
            int rc = (kk + la3) * 136, rd = (kk + 4 + la3) * 136;
            uint32_t bf[4][2];
            #pragma unroll
            for (int nt = 0; nt < 4; nt++) {
                int n = wn + nt * 8 + l4;
                bf[nt][0] = Bb[rc + n];
                bf[nt][1] = Bb[rd + n];
            }
            #pragma unroll
            for (int mt = 0; mt < 4; mt++) {
                int m = wm + mt * 16 + l4;
                uint32_t a0 = Ab[m * 20 + kk + la3];
                uint32_t a1 = Ab[(m + 8) * 20 + kk + la3];
                uint32_t a2 = Ab[m * 20 + kk + 4 + la3];
                uint32_t a3 = Ab[(m + 8) * 20 + kk + 4 + la3];
                #pragma unroll
                for (int nt = 0; nt < 4; nt++)
                    mma8(acc[mt][nt], a0, a1, a2, a3, bf[nt][0], bf[nt][1]);
            }
        }
        __syncthreads();
    }
    #undef G_FILL

    #pragma unroll
    for (int mt = 0; mt < 4; mt++) {
        int r = row0 + wm + mt * 16 + l4;
        #pragma unroll
        for (int nt = 0; nt < 4; nt++) {
            int cb = col0 + wn + nt * 8 + 2 * la3;
            float v0 = acc[mt][nt][0] + bias[cb];
            float v1 = acc[mt][nt][1] + bias[cb + 1];
            float v2 = acc[mt][nt][2] + bias[cb];
            float v3 = acc[mt][nt][3] + bias[cb + 1];
            if (MODE == 0) {
                float* C = (float*)Cout;
                C[(size_t)r       * HH + cb    ] = v0;
                C[(size_t)r       * HH + cb + 1] = v1;
                C[(size_t)(r + 8) * HH + cb    ] = v2;
                C[(size_t)(r + 8) * HH + cb + 1] = v3;
            } else {
                // V: transposed, keys PHI-permuted (r&15 = l4 < 8, so PHI(r+8)=PHI(r)+2)
                uint32_t* VtP = (uint32_t*)Cout;
                int bI = r >> 11, s = r & 2047;
                int hI = cb >> 6, d = cb & 63;
                int pos = 16 * (s >> 4) + 4 * ((s >> 1) & 3) + 2 * ((s >> 3) & 1) + (s & 1);
                size_t hb = (size_t)(bI * NH + hI) * HD;
                VtP[(hb + d)     * SS + pos    ] = f2tf32(v0);
                VtP[(hb + d + 1) * SS + pos    ] = f2tf32(v1);
                VtP[(hb + d)     * SS + pos + 2] = f2tf32(v2);
                VtP[(hb + d + 1) * SS + pos + 2] = f2tf32(v3);
            }
        }
    }
}

// ---------------------------------------------------------------------------
// D = x @ Wd + bd in 3xBF16 (m16n8k16), cp.async double-buffered.
// 256 thr, 64x32 warp tiles, reg-capped for 2 CTAs/SM. Quad-permuted output.
// ---------------------------------------------------------------------------
__global__ __launch_bounds__(256, 2) void gemm_bf3(const uint32_t* __restrict__ AHL,
                                                   const uint32_t* __restrict__ WHL,
                                                   const float* __restrict__ bias,
                                                   uint32_t* __restrict__ Dout) {
    extern __shared__ uint32_t sm[];
    const int ASZ = 128 * 40, BSZ = 16 * 264;
    uint32_t* Asm = sm;
    uint32_t* Bsm = sm + 2 * ASZ;
    int tid = threadIdx.x, lane = tid & 31, w = tid >> 5;
    int la3 = lane & 3, l4 = lane >> 2;
    int wm = (w & 1) * 64, wn = (w >> 1) * 32;
    int row0 = blockIdx.y * 128, col0 = blockIdx.x * 128;

    uint32_t asb = smem_u32(Asm), bsb = smem_u32(Bsm);
    float acc[4][4][4] = {};

    #define B_FILL(T) do {                                                       \
        int u0 = (T) * 32, p0 = (T) * 16, bf = (T) & 1;                          \
        _Pragma("unroll")                                                        \
        for (int i = 0; i < 4; i++) {                                            \
            int f = tid + i * 256;                                               \
            int r = f >> 3, j = f & 7;                                           \
            cp16(asb + (bf * ASZ + r * 40 + 4 * j) * 4,                          \
                 AHL + (size_t)(row0 + r) * HH + u0 + 4 * j);                    \
        }                                                                        \
        _Pragma("unroll")                                                        \
        for (int i = 0; i < 4; i++) {                                            \
            int f = tid + i * 256;                                               \
            int p = f >> 6, j = f & 63;                                          \
            cp16(bsb + (bf * BSZ + p * 264 + 4 * j) * 4,                         \
                 WHL + (size_t)(p0 + p) * 2048 + 2 * col0 + 4 * j);              \
        }                                                                        \
    } while (0)

    B_FILL(0); cp_commit();

    for (int t = 0; t < HH / 32; t++) {
        if (t + 1 < HH / 32) { B_FILL(t + 1); cp_commit(); cp_wait<1>(); }
        else                 { cp_wait<0>(); }
        __syncthreads();
        const uint32_t* Ab = Asm + (t & 1) * ASZ;
        const uint32_t* Bb = Bsm + (t & 1) * BSZ;

        #pragma unroll
        for (int K = 0; K < 2; K++) {
            int pb = K * 8;
            uint2 Bf0[4], Bf1[4];
            #pragma unroll
            for (int nt = 0; nt < 4; nt++) {
                int n = wn + nt * 8 + l4;
                Bf0[nt] = *(const uint2*)&Bb[(pb + la3)     * 264 + 2 * n];
                Bf1[nt] = *(const uint2*)&Bb[(pb + 4 + la3) * 264 + 2 * n];
            }
            #pragma unroll
            for (int mt = 0; mt < 4; mt++) {
                int m = wm + mt * 16 + l4;
                uint2 A0 = *(const uint2*)&Ab[m       * 40 + 2 * (pb + la3)];
                uint2 A1 = *(const uint2*)&Ab[(m + 8) * 40 + 2 * (pb + la3)];
                uint2 A2 = *(const uint2*)&Ab[m       * 40 + 2 * (pb + 4 + la3)];
                uint2 A3 = *(const uint2*)&Ab[(m + 8) * 40 + 2 * (pb + 4 + la3)];
                #pragma unroll
                for (int nt = 0; nt < 4; nt++) {
                    mma16(acc[mt][nt], A0.x, A1.x, A2.x, A3.x, Bf0[nt].x, Bf1[nt].x);
                    mma16(acc[mt][nt], A0.x, A1.x, A2.x, A3.x, Bf0[nt].y, Bf1[nt].y);
                    mma16(acc[mt][nt], A0.y, A1.y, A2.y, A3.y, Bf0[nt].x, Bf1[nt].x);
                }
            }
        }
        __syncthreads();
    }
    #undef B_FILL

    #pragma unroll
    for (int mt = 0; mt < 4; mt++) {
        int r = row0 + wm + mt * 16 + l4;
        #pragma unroll
        for (int nt = 0; nt < 4; nt++) {
            int cb = col0 + wn + nt * 8 + 2 * la3;
            int p = cb >> 1;                 // global dim-pair index
            int head = p >> 5, q = p & 31;
            int off = head * 64 + 16 * (q >> 3) + 4 * (q & 3) + 2 * ((q >> 2) & 1);
            float v0 = acc[mt][nt][0] + bias[cb];
            float v1 = acc[mt][nt][1] + bias[cb + 1];
            float v2 = acc[mt][nt][2] + bias[cb];
            float v3 = acc[mt][nt][3] + bias[cb + 1];
            uint32_t h, l;
            bfsplit2(v0, v1, h, l);
            *(uint2*)&Dout[(size_t)r * HH + off] = make_uint2(h, l);
            bfsplit2(v2, v3, h, l);
            *(uint2*)&Dout[(size_t)(r + 8) * HH + off] = make_uint2(h, l);
        }
    }
}

// ---------------------------------------------------------------------------
// Fused anti-causal gaussian attention. QK 3xBF16, PV tf32.
// All fragment traffic 128-bit; rows width 64 with ^((row&1)<<4) swizzle.
// Grid: (h, b, qb) with qb SLOWEST -> longest CTAs launch first (LPT).
// Smem: Dk[64][64] + Vp[64][64] + Ps[64][64] = 48KB -> 4 CTAs/SM.
// ---------------------------------------------------------------------------
__global__ __launch_bounds__(128, 4) void attn_tc(const uint32_t* __restrict__ DH,
                                                  const uint32_t* __restrict__ VtP,
                                                  uint32_t* __restrict__ C) {
    extern __shared__ uint32_t sm[];
    const int DK0 = 0;                 // [64][64] bf16 pairs, quad-permuted
    const int VT0 = 64 * 64;           // [64][64] tf32, PHI keys
    const int PS0 = VT0 + 64 * 64;     // [64][64] tf32, PHI keys

    int tid = threadIdx.x, lane = tid & 31, w = tid >> 5;
    int la3 = lane & 3, l4 = lane >> 2;
    int h = blockIdx.x, b = blockIdx.y, q0 = blockIdx.z * 64;
    const uint32_t* DHb = DH + (size_t)b * SS * HH + h * 64;
    const uint32_t* Vb  = VtP + (size_t)(b * NH + h) * HD * SS;
    int qrow = w * 16 + l4;
    int sw = (l4 & 1) << 4;

    uint32_t smb = smem_u32(sm);
    uint32_t dkb = smb + DK0 * 4;
    uint32_t vtb = smb + VT0 * 4;

    uint32_t aH[4][4], aL[4][4];
    {
        const uint32_t* r0 = DHb + (size_t)(q0 + qrow) * HH;
        const uint32_t* r8 = r0 + (size_t)8 * HH;
        #pragma unroll
        for (int K = 0; K < 4; K++) {
            uint4 Q0 = *(const uint4*)&r0[16 * K + 4 * la3];
            uint4 Q8 = *(const uint4*)&r8[16 * K + 4 * la3];
            aH[K][0] = Q0.x; aL[K][0] = Q0.y; aH[K][2] = Q0.z; aL[K][2] = Q0.w;
            aH[K][1] = Q8.x; aL[K][1] = Q8.y; aH[K][3] = Q8.z; aL[K][3] = Q8.w;
        }
    }

    float ctx[8][4] = {};
    int nT = (SS - q0) / 64;

    #define FILL_DK(T) do {                                                      \
        int k0t = q0 + (T) * 64;                                                 \
        _Pragma("unroll")                                                        \
        for (int i = 0; i < 8; i++) {                                            \
            int idx = tid + i * 128;                                             \
            int r = idx >> 4, j = idx & 15;                                      \
            cp16(dkb + (r * 64 + ((4 * j) ^ ((r & 1) << 4))) * 4,                \
                 DHb + (size_t)(k0t + r) * HH + 4 * j);                          \
        }                                                                        \
    } while (0)
    #define FILL_V(T) do {                                                       \
        int k0t = q0 + (T) * 64;                                                 \
        _Pragma("unroll")                                                        \
        for (int i = 0; i < 8; i++) {                                            \
            int idx = tid + i * 128;                                             \
            int d = idx >> 4, j = idx & 15;                                      \
            cp16(vtb + (d * 64 + ((4 * j) ^ ((d & 1) << 4))) * 4,                \
                 Vb + (size_t)d * SS + k0t + 4 * j);                             \
        }                                                                        \
    } while (0)

    FILL_DK(0); cp_commit();
    FILL_V(0);  cp_commit();

    for (int t = 0; t < nT; t++) {
        int k0 = q0 + t * 64;
        cp_wait<1>();          // Dk(t) resident
        __syncthreads();

        const uint32_t* Dk = sm + DK0;
        const uint32_t* Vp = sm + VT0;
        uint32_t* Pw = sm + PS0;

        // ---- QK: S[16q x 64k] per warp, 3xBF16 over d=64 (all LDS.128) ----
        float s4[8][4] = {};
        #pragma unroll
        for (int K = 0; K < 4; K++) {
            #pragma unroll
            for (int nt = 0; nt < 8; nt++) {
                const uint32_t* br = Dk + (nt * 8 + l4) * 64;
                uint4 Dq = *(const uint4*)&br[(16 * K + 4 * la3) ^ sw];
                mma16(s4[nt], aH[K][0], aH[K][1], aH[K][2], aH[K][3], Dq.x, Dq.z);
                mma16(s4[nt], aH[K][0], aH[K][1], aH[K][2], aH[K][3], Dq.y, Dq.w);
                mma16(s4[nt], aL[K][0], aL[K][1], aL[K][2], aL[K][3], Dq.x, Dq.z);
            }
        }

        __syncthreads();                       // all warps done reading Dk
        if (t + 1 < nT) FILL_DK(t + 1);        // overlaps mask + PV
        cp_commit();

        // ---- mask (k > q strictly) + exp -> Ps (PHI layout, STS.128) ----
        #pragma unroll
        for (int kt2 = 0; kt2 < 4; kt2++) {
            int nt0 = 2 * kt2, nt1 = nt0 + 1;
            int kg0 = k0 + nt0 * 8 + 2 * la3;
            int kg1 = k0 + nt1 * 8 + 2 * la3;
            int qa = q0 + qrow, qb8 = qa + 8;
            float e0 = (kg0     > qa) ? __expf(-0.5f * s4[nt0][0]) : 0.0f;
            float e1 = (kg0 + 1 > qa) ? __expf(-0.5f * s4[nt0][1]) : 0.0f;
            float e2 = (kg1     > qa) ? __expf(-0.5f * s4[nt1][0]) : 0.0f;
            float e3 = (kg1 + 1 > qa) ? __expf(-0.5f * s4[nt1][1]) : 0.0f;
            *(uint4*)&Pw[qrow * 64 + ((16 * kt2 + 4 * la3) ^ sw)] =
                make_uint4(f2tf32(e0), f2tf32(e1), f2tf32(e2), f2tf32(e3));
            e0 = (kg0     > qb8) ? __expf(-0.5f * s4[nt0][2]) : 0.0f;
            e1 = (kg0 + 1 > qb8) ? __expf(-0.5f * s4[nt0][3]) : 0.0f;
            e2 = (kg1     > qb8) ? __expf(-0.5f * s4[nt1][2]) : 0.0f;
            e3 = (kg1 + 1 > qb8) ? __expf(-0.5f * s4[nt1][3]) : 0.0f;
            *(uint4*)&Pw[(qrow + 8) * 64 + ((16 * kt2 + 4 * la3) ^ sw)] =
                make_uint4(f2tf32(e0), f2tf32(e1), f2tf32(e2), f2tf32(e3));
        }
        __syncwarp();   // Pw rows are warp-private

        cp_wait<1>();          // V(t) resident
        __syncthreads();

        // ---- PV: ctx += P @ V over 64 keys (all LDS.128) ----
        #pragma unroll
        for (int kt2 = 0; kt2 < 4; kt2++) {
            uint4 Pa = *(const uint4*)&Pw[qrow * 64 + ((16 * kt2 + 4 * la3) ^ sw)];
            uint4 Pb = *(const uint4*)&Pw[(qrow + 8) * 64 + ((16 * kt2 + 4 * la3) ^ sw)];
            #pragma unroll
            for (int nt = 0; nt < 8; nt++) {
                int vr = nt * 8 + l4;
                uint4 Vq = *(const uint4*)&Vp[vr * 64 + ((16 * kt2 + 4 * la3) ^ ((vr & 1) << 4))];
                mma8(ctx[nt], Pa.x, Pb.x, Pa.y, Pb.y, Vq.x, Vq.y);
                mma8(ctx[nt], Pa.z, Pb.z, Pa.w, Pb.w, Vq.z, Vq.w);
            }
        }

        __syncthreads();                       // all warps done reading Vp/Ps
        if (t + 1 < nT) FILL_V(t + 1);         // overlaps next QK
        cp_commit();
    }

    // Store ctx as tf32 in merged [B,S,H] layout
    uint32_t* Cb = C + (size_t)b * SS * HH + h * HD;
    #pragma unroll
    for (int nt = 0; nt < 8; nt++) {
        int r = q0 + qrow;
        int c = nt * 8 + 2 * la3;
        *(uint2*)&Cb[(size_t)r       * HH + c] = make_uint2(f2tf32(ctx[nt][0]), f2tf32(ctx[nt][1]));
        *(uint2*)&Cb[(size_t)(r + 8) * HH + c] = make_uint2(f2tf32(ctx[nt][2]), f2tf32(ctx[nt][3]));
    }
    #undef FILL_DK
    #undef FILL_V
}

static const int ATTN_SMEM = (3 * 64 * 64) * 4;                  // 49152 B
static const int BF3_SMEM  = (2 * 128 * 40 + 2 * 16 * 264) * 4;  // 74752 B

extern "C" void kernel_launch(void* const* d_in, const int* in_sizes, int n_in,
                              void* d_out, int out_size) {
    const float* x  = (const float*)d_in[0];
    const float* Wq = (const float*)d_in[1];
    const float* bq = (const float*)d_in[2];
    const float* Wk = (const float*)d_in[3];
    const float* bk = (const float*)d_in[4];
    const float* Wv = (const float*)d_in[5];
    const float* bv = (const float*)d_in[6];
    const float* Wo = (const float*)d_in[7];
    const float* bo = (const float*)d_in[8];
    float* out = (float*)d_out;

    uint32_t *pxTF, *pxHL, *pWdHL, *pWvTF, *pWoTF, *pDHL, *pVtP, *pC;
    float *pbd;
    cudaGetSymbolAddress((void**)&pxTF,  g_xTF);
    cudaGetSymbolAddress((void**)&pxHL,  g_xHL);
    cudaGetSymbolAddress((void**)&pWdHL, g_WdHL);
    cudaGetSymbolAddress((void**)&pWvTF, g_WvTF);
    cudaGetSymbolAddress((void**)&pWoTF, g_WoTF);
    cudaGetSymbolAddress((void**)&pbd,   g_bd);
    cudaGetSymbolAddress((void**)&pDHL,  g_DHL);
    cudaGetSymbolAddress((void**)&pVtP,  g_VtP);
    cudaGetSymbolAddress((void**)&pC,    g_C);

    static bool attr_set = false;
    if (!attr_set) {
        cudaFuncSetAttribute(attn_tc, cudaFuncAttributeMaxDynamicSharedMemorySize, ATTN_SMEM);
        cudaFuncSetAttribute(gemm_bf3, cudaFuncAttributeMaxDynamicSharedMemorySize, BF3_SMEM);
        attr_set = true;
    }

    // 1. prep
    prep_x  <<<(MM * HH / 4) / 256, 256>>>(x);
    prep_wd <<<(512 * 1024) / 256, 256>>>(Wq, Wk, bq, bk);
    prep_tf2<<<dim3((HH * HH / 4) / 256, 2), 256>>>(Wv, pWvTF, Wo, pWoTF);

    // 2. D = x @ Wd + bd (3xBF16) ; V = x @ Wv + bv (tf32, direct PHI VtP out)
    dim3 ggrid(HH / 128, MM / 128);
    gemm_bf3<<<ggrid, 256, BF3_SMEM>>>(pxHL, pWdHL, pbd, pDHL);
    gemm_tc<3><<<ggrid, 256>>>(pxTF, pWvTF, bv, pVtP);

    // 3. fused attention (LPT: qb slowest-varying, longest first)
    dim3 agrid(NH, BB, SS / 64);
    attn_tc<<<agrid, 128, ATTN_SMEM>>>(pDHL, pVtP, pC);

    // 4. out = ctx @ Wo + bo (tf32)
    gemm_tc<0><<<ggrid, 256>>>(pC, pWoTF, bo, out);
}

// round 16
// speedup vs baseline: 1.6059x; 1.0147x over previous
#include <cuda_runtime.h>
#include <cuda_bf16.h>
#include <cstdint>

#define BB 2
#define SS 2048
#define HH 1024
#define NH 16
#define HD 64
#define MM (BB*SS)   // 4096 rows

// Scratch (allocation is forbidden; use __device__ globals)
__device__ uint32_t g_xTF[(size_t)MM*HH];         // x as tf32
__device__ uint32_t g_xHL[(size_t)MM*HH];         // x bf16 hi/lo, quad-permuted per 8-pair group
__device__ uint32_t g_WdT[(size_t)HH*1024];       // (Wq-Wk)^T [n][k-pairs hi/lo, quad-permuted]
__device__ uint32_t g_WvTF[(size_t)HH*HH];        // Wv as tf32
__device__ uint32_t g_WoTF[(size_t)HH*HH];        // Wo as tf32
__device__ float    g_bd[HH];
__device__ uint32_t g_DHL[(size_t)MM*HH];         // D, bf16 hi/lo, quad-permuted per head
__device__ uint32_t g_VtP[(size_t)BB*NH*HD*SS];   // V^T tf32, keys in PHI order, per (b,h)
__device__ uint32_t g_C[(size_t)MM*HH];           // ctx as tf32

__device__ __forceinline__ uint32_t f2tf32(float x) {
    uint32_t r;
    asm("cvt.rna.tf32.f32 %0, %1;" : "=r"(r) : "f"(x));
    return r;
}
__device__ __forceinline__ uint32_t bfpack(float x0, float x1) {
    __nv_bfloat162 t;
    t.x = __float2bfloat16_rn(x0);
    t.y = __float2bfloat16_rn(x1);
    return *(uint32_t*)&t;
}
__device__ __forceinline__ void bfsplit2(float x0, float x1, uint32_t& hi, uint32_t& lo) {
    __nv_bfloat16 h0 = __float2bfloat16_rn(x0), h1 = __float2bfloat16_rn(x1);
    float r0 = x0 - __bfloat162float(h0), r1 = x1 - __bfloat162float(h1);
    __nv_bfloat162 th; th.x = h0; th.y = h1;
    hi = *(uint32_t*)&th;
    lo = bfpack(r0, r1);
}
__device__ __forceinline__ void mma8(float* c,
                                     uint32_t a0, uint32_t a1, uint32_t a2, uint32_t a3,
                                     uint32_t b0, uint32_t b1) {
    asm volatile(
        "mma.sync.aligned.m16n8k8.row.col.f32.tf32.tf32.f32 "
        "{%0,%1,%2,%3}, {%4,%5,%6,%7}, {%8,%9}, {%0,%1,%2,%3};"
        : "+f"(c[0]), "+f"(c[1]), "+f"(c[2]), "+f"(c[3])
        : "r"(a0), "r"(a1), "r"(a2), "r"(a3), "r"(b0), "r"(b1));
}
__device__ __forceinline__ void mma16(float* c,
                                      uint32_t a0, uint32_t a1, uint32_t a2, uint32_t a3,
                                      uint32_t b0, uint32_t b1) {
    asm volatile(
        "mma.sync.aligned.m16n8k16.row.col.f32.bf16.bf16.f32 "
        "{%0,%1,%2,%3}, {%4,%5,%6,%7}, {%8,%9}, {%0,%1,%2,%3};"
        : "+f"(c[0]), "+f"(c[1]), "+f"(c[2]), "+f"(c[3])
        : "r"(a0), "r"(a1), "r"(a2), "r"(a3), "r"(b0), "r"(b1));
}
__device__ __forceinline__ uint32_t smem_u32(const void* p) {
    uint32_t a;
    asm("{ .reg .u64 t; cvta.to.shared.u64 t, %1; cvt.u32.u64 %0, t; }" : "=r"(a) : "l"(p));
    return a;
}
__device__ __forceinline__ void cp16(uint32_t dst, const void* src) {
    asm volatile("cp.async.ca.shared.global [%0], [%1], 16;" :: "r"(dst), "l"(src));
}
__device__ __forceinline__ void cp_commit() { asm volatile("cp.async.commit_group;"); }
template<int N> __device__ __forceinline__ void cp_wait() {
    asm volatile("cp.async.wait_group %0;" :: "n"(N));
}

// ---------------------------------------------------------------------------
// Prep kernels
// ---------------------------------------------------------------------------
// x -> tf32 (linear) + bf16 hi/lo with quad permutation:
// global pair P -> u32 (P>>3)*16 + 4*(P&3) + 2*((P>>2)&1), {hi,lo} adjacent.
__global__ void prep_x(const float* __restrict__ x,
                       const float* __restrict__ bq, const float* __restrict__ bk) {
    int i = blockIdx.x * blockDim.x + threadIdx.x;   // over MM*HH/4
    float4 v = ((const float4*)x)[i];
    ((uint4*)g_xTF)[i] = make_uint4(f2tf32(v.x), f2tf32(v.y), f2tf32(v.z), f2tf32(v.w));
    uint32_t h0, l0, h1, l1;
    bfsplit2(v.x, v.y, h0, l0);
    bfsplit2(v.z, v.w, h1, l1);
    int P = 2 * i;                                   // even; P,P+1 in same 8-group
    size_t base = (size_t)(P >> 3) * 16;
    int p0 = P & 7, p1 = p0 + 1;
    *(uint2*)&g_xHL[base + 4 * (p0 & 3) + 2 * ((p0 >> 2) & 1)] = make_uint2(h0, l0);
    *(uint2*)&g_xHL[base + 4 * (p1 & 3) + 2 * ((p1 >> 2) & 1)] = make_uint2(h1, l1);
    if (i < HH) g_bd[i] = bq[i] - bk[i];
}
// (Wq-Wk)^T: tiled transpose + bf16 split + quad permutation -> g_WdT[n][1024]
__global__ __launch_bounds__(256) void prep_wdT(const float* __restrict__ Wq,
                                                const float* __restrict__ Wk) {
    __shared__ float t[32][33];
    int k0 = blockIdx.x * 32, n0 = blockIdx.y * 32;
    int tid = threadIdx.x;
    int tn = tid & 31, tk = tid >> 5;
    #pragma unroll
    for (int i = 0; i < 4; i++) {
        int k = tk + i * 8;
        size_t idx = (size_t)(k0 + k) * HH + n0 + tn;
        t[k][tn] = Wq[idx] - Wk[idx];
    }
    __syncthreads();
    #pragma unroll
    for (int i = 0; i < 2; i++) {
        int idx = tid + i * 256;                     // 0..511
        int n = idx >> 4, kp = idx & 15;             // local k-pair
        int P = (k0 >> 1) + kp;                      // global k-pair
        int p = P & 7;
        uint32_t h, l;
        bfsplit2(t[2 * kp][n], t[2 * kp + 1][n], h, l);
        size_t dst = (size_t)(n0 + n) * 1024 + (size_t)(P >> 3) * 16
                   + 4 * (p & 3) + 2 * ((p >> 2) & 1);
        *(uint2*)&g_WdT[dst] = make_uint2(h, l);
    }
}
__global__ void prep_tf2(const float* __restrict__ s0, uint32_t* __restrict__ d0,
                         const float* __restrict__ s1, uint32_t* __restrict__ d1) {
    int i = blockIdx.x * blockDim.x + threadIdx.x;   // over HH*HH/4
    const float* src = blockIdx.y ? s1 : s0;
    uint32_t* dst = blockIdx.y ? d1 : d0;
    float4 v = ((const float4*)src)[i];
    ((uint4*)dst)[i] = make_uint4(f2tf32(v.x), f2tf32(v.y), f2tf32(v.z), f2tf32(v.w));
}

// ---------------------------------------------------------------------------
// tf32 GEMM, cp.async double-buffered (R11-proven, unchanged).
// MODE 0: fp32 out (final). MODE 3: V out -> g_VtP transposed, PHI keys.
// ---------------------------------------------------------------------------
template<int MODE>
__global__ __launch_bounds__(256, 2) void gemm_tc(const uint32_t* __restrict__ A,
                                                  const uint32_t* __restrict__ W,
                                                  const float* __restrict__ bias,
                                                  void* __restrict__ Cout) {
    const int ASZ = 128 * 20, BSZ = 16 * 136;
    __shared__ uint32_t As[2 * ASZ];
    __shared__ uint32_t Bs[2 * BSZ];
    int tid = threadIdx.x, lane = tid & 31, w = tid >> 5;
    int la3 = lane & 3, l4 = lane >> 2;
    int wm = (w & 1) * 64, wn = (w >> 1) * 32;
    int row0 = blockIdx.y * 128, col0 = blockIdx.x * 128;

    uint32_t asb = smem_u32(As), bsb = smem_u32(Bs);
    float acc[4][4][4] = {};

    #define G_FILL(T) do {                                                       \
        int k0 = (T) * 16, bf = (T) & 1;                                         \
        _Pragma("unroll")                                                        \
        for (int i = 0; i < 2; i++) {                                            \
            int f = tid + i * 256;                                               \
            int r = f >> 2, j = f & 3;                                           \
            cp16(asb + (bf * ASZ + r * 20 + 4 * j) * 4,                          \
                 A + (size_t)(row0 + r) * HH + k0 + 4 * j);                      \
        }                                                                        \
        _Pragma("unroll")                                                        \
        for (int i = 0; i < 2; i++) {                                            \
            int f = tid + i * 256;                                               \
            int r = f >> 5, j = f & 31;                                          \
            cp16(bsb + (bf * BSZ + r * 136 + 4 * j) * 4,                         \
                 W + (size_t)(k0 + r) * HH + col0 + 4 * j);                      \
        }                                                                        \
    } while (0)

    G_FILL(0); cp_commit();

    for (int t = 0; t < HH / 16; t++) {
        if (t + 1 < HH / 16) { G_FILL(t + 1); cp_commit(); cp_wait<1>(); }
        else                 { cp_wait<0>(); }
        __syncthreads();
        const uint32_t* Ab = As + (t & 1) * ASZ;
        const uint32_t* Bb = Bs + (t & 1) * BSZ;

        #pragma unroll
        for (int kk = 0; kk < 16; kk += 8) {
            int rc = (kk + la3) * 136, rd = (kk + 4 + la3) * 136;
            uint32_t bf[4][2];
            #pragma unroll
            for (int nt = 0; nt < 4; nt++) {
                int n = wn + nt * 8 + l4;
                bf[nt][0] = Bb[rc + n];
                bf[nt][1] = Bb[rd + n];
            }
            #pragma unroll
            for (int mt = 0; mt < 4; mt++) {
                int m = wm + mt * 16 + l4;
                uint32_t a0 = Ab[m * 20 + kk + la3];
                uint32_t a1 = Ab[(m + 8) * 20 + kk + la3];
                uint32_t a2 = Ab[m * 20 + kk + 4 + la3];
                uint32_t a3 = Ab[(m + 8) * 20 + kk + 4 + la3];
                #pragma unroll
                for (int nt = 0; nt < 4; nt++)
                    mma8(acc[mt][nt], a0, a1, a2, a3, bf[nt][0], bf[nt][1]);
            }
        }
        __syncthreads();
    }
    #undef G_FILL

    #pragma unroll
    for (int mt = 0; mt < 4; mt++) {
        int r = row0 + wm + mt * 16 + l4;
        #pragma unroll
        for (int nt = 0; nt < 4; nt++) {
            int cb = col0 + wn + nt * 8 + 2 * la3;
            float v0 = acc[mt][nt][0] + bias[cb];
            float v1 = acc[mt][nt][1] + bias[cb + 1];
            float v2 = acc[mt][nt][2] + bias[cb];
            float v3 = acc[mt][nt][3] + bias[cb + 1];
            if (MODE == 0) {
                float* C = (float*)Cout;
                C[(size_t)r       * HH + cb    ] = v0;
                C[(size_t)r       * HH + cb + 1] = v1;
                C[(size_t)(r + 8) * HH + cb    ] = v2;
                C[(size_t)(r + 8) * HH + cb + 1] = v3;
            } else {
                uint32_t* VtP = (uint32_t*)Cout;
                int bI = r >> 11, s = r & 2047;
                int hI = cb >> 6, d = cb & 63;
                int pos = 16 * (s >> 4) + 4 * ((s >> 1) & 3) + 2 * ((s >> 3) & 1) + (s & 1);
                size_t hb = (size_t)(bI * NH + hI) * HD;
                VtP[(hb + d)     * SS + pos    ] = f2tf32(v0);
                VtP[(hb + d + 1) * SS + pos    ] = f2tf32(v1);
                VtP[(hb + d)     * SS + pos + 2] = f2tf32(v2);
                VtP[(hb + d + 1) * SS + pos + 2] = f2tf32(v3);
            }
        }
    }
}

// ---------------------------------------------------------------------------
// D = x @ Wd + bd in 3xBF16 (m16n8k16). All fragments LDS.128 via quad-
// permuted gmem layouts (g_xHL, g_WdT). Smem rows width 32 u32 with
// ^((row&1)<<4) swizzle (conflict-free, bank-verified). 24 LDS.128 + 96 mma16
// per stage (was 48 LDS.64). Bit-identical mma order (hh, hl, lh).
// Quad-permuted D output (unchanged).
// ---------------------------------------------------------------------------
__global__ __launch_bounds__(256, 2) void gemm_bf3(const uint32_t* __restrict__ AHL,
                                                   const uint32_t* __restrict__ WT,
                                                   const float* __restrict__ bias,
                                                   uint32_t* __restrict__ Dout) {
    extern __shared__ uint32_t sm[];
    const int ASZ = 128 * 32, STG = 2 * ASZ;     // A + B per stage = 8192 u32
    int tid = threadIdx.x, lane = tid & 31, w = tid >> 5;
    int la3 = lane & 3, l4 = lane >> 2;
    int wm = (w & 1) * 64, wn = (w >> 1) * 32;
    int row0 = blockIdx.y * 128, col0 = blockIdx.x * 128;

    uint32_t smb = smem_u32(sm);
    float acc[4][4][4] = {};

    #define B_FILL(T) do {                                                       \
        int u0 = (T) * 32, bf = (T) & 1;                                         \
        uint32_t ab = smb + bf * STG * 4;                                        \
        uint32_t bb2 = ab + ASZ * 4;                                             \
        _Pragma("unroll")                                                        \
        for (int i = 0; i < 4; i++) {                                            \
            int c = tid + i * 256;                                               \
            int r = c >> 3, j = c & 7;                                           \
            uint32_t off = (r * 32 + ((4 * j) ^ ((r & 1) << 4))) * 4;            \
            cp16(ab + off,  AHL + (size_t)(row0 + r) * 1024 + u0 + 4 * j);       \
            cp16(bb2 + off, WT  + (size_t)(col0 + r) * 1024 + u0 + 4 * j);       \
        }                                                                        \
    } while (0)

    B_FILL(0); cp_commit();

    for (int t = 0; t < HH / 32; t++) {
        if (t + 1 < HH / 32) { B_FILL(t + 1); cp_commit(); cp_wait<1>(); }
        else                 { cp_wait<0>(); }
        __syncthreads();
        const uint32_t* Ab = sm + (t & 1) * STG;
        const uint32_t* Bb = Ab + ASZ;
        int sx = (l4 & 1) << 4;

        #pragma unroll
        for (int ks = 0; ks < 2; ks++) {
            int g = (ks * 16 + 4 * la3) ^ sx;
            uint4 Bq[4];
            #pragma unroll
            for (int nt = 0; nt < 4; nt++)
                Bq[nt] = *(const uint4*)&Bb[(wn + nt * 8 + l4) * 32 + g];
            #pragma unroll
            for (int mt = 0; mt < 4; mt++) {
                int m = wm + mt * 16 + l4;
                uint4 Aq0 = *(const uint4*)&Ab[m       * 32 + g];
                uint4 Aq8 = *(const uint4*)&Ab[(m + 8) * 32 + g];
                #pragma unroll
                for (int nt = 0; nt < 4; nt++) {
                    mma16(acc[mt][nt], Aq0.x, Aq8.x, Aq0.z, Aq8.z, Bq[nt].x, Bq[nt].z);
                    mma16(acc[mt][nt], Aq0.x, Aq8.x, Aq0.z, Aq8.z, Bq[nt].y, Bq[nt].w);
                    mma16(acc[mt][nt], Aq0.y, Aq8.y, Aq0.w, Aq8.w, Bq[nt].x, Bq[nt].z);
                }
            }
        }
        __syncthreads();
    }
    #undef B_FILL

    #pragma unroll
    for (int mt = 0; mt < 4; mt++) {
        int r = row0 + wm + mt * 16 + l4;
        #pragma unroll
        for (int nt = 0; nt < 4; nt++) {
            int cb = col0 + wn + nt * 8 + 2 * la3;
            int p = cb >> 1;                 // global dim-pair index
            int head = p >> 5, q = p & 31;
            int off = head * 64 + 16 * (q >> 3) + 4 * (q & 3) + 2 * ((q >> 2) & 1);
            float v0 = acc[mt][nt][0] + bias[cb];
            float v1 = acc[mt][nt][1] + bias[cb + 1];
            float v2 = acc[mt][nt][2] + bias[cb];
            float v3 = acc[mt][nt][3] + bias[cb + 1];
            uint32_t h, l;
            bfsplit2(v0, v1, h, l);
            *(uint2*)&Dout[(size_t)r * HH + off] = make_uint2(h, l);
            bfsplit2(v2, v3, h, l);
            *(uint2*)&Dout[(size_t)(r + 8) * HH + off] = make_uint2(h, l);
        }
    }
}

// ---------------------------------------------------------------------------
// Fused anti-causal gaussian attention. QK 3xBF16, PV tf32. (R11-proven)
// ---------------------------------------------------------------------------
__global__ __launch_bounds__(128, 4) void attn_tc(const uint32_t* __restrict__ DH,
                                                  const uint32_t* __restrict__ VtP,
                                                  uint32_t* __restrict__ C) {
    extern __shared__ uint32_t sm[];
    const int DK0 = 0;                 // [64][64] bf16 pairs, quad-permuted
    const int VT0 = 64 * 64;           // [64][64] tf32, PHI keys
    const int PS0 = VT0 + 64 * 64;     // [64][64] tf32, PHI keys

    int tid = threadIdx.x, lane = tid & 31, w = tid >> 5;
    int la3 = lane & 3, l4 = lane >> 2;
    int h = blockIdx.x, b = blockIdx.y, q0 = blockIdx.z * 64;
    const uint32_t* DHb = DH + (size_t)b * SS * HH + h * 64;
    const uint32_t* Vb  = VtP + (size_t)(b * NH + h) * HD * SS;
    int qrow = w * 16 + l4;
    int sw = (l4 & 1) << 4;

    uint32_t smb = smem_u32(sm);
    uint32_t dkb = smb + DK0 * 4;
    uint32_t vtb = smb + VT0 * 4;

    uint32_t aH[4][4], aL[4][4];
    {
        const uint32_t* r0 = DHb + (size_t)(q0 + qrow) * HH;
        const uint32_t* r8 = r0 + (size_t)8 * HH;
        #pragma unroll
        for (int K = 0; K < 4; K++) {
            uint4 Q0 = *(const uint4*)&r0[16 * K + 4 * la3];
            uint4 Q8 = *(const uint4*)&r8[16 * K + 4 * la3];
            aH[K][0] = Q0.x; aL[K][0] = Q0.y; aH[K][2] = Q0.z; aL[K][2] = Q0.w;
            aH[K][1] = Q8.x; aL[K][1] = Q8.y; aH[K][3] = Q8.z; aL[K][3] = Q8.w;
        }
    }

    float ctx[8][4] = {};
    int nT = (SS - q0) / 64;

    #define FILL_DK(T) do {                                                      \
        int k0t = q0 + (T) * 64;                                                 \
        _Pragma("unroll")                                                        \
        for (int i = 0; i < 8; i++) {                                            \
            int idx = tid + i * 128;                                             \
            int r = idx >> 4, j = idx & 15;                                      \
            cp16(dkb + (r * 64 + ((4 * j) ^ ((r & 1) << 4))) * 4,                \
                 DHb + (size_t)(k0t + r) * HH + 4 * j);                          \
        }                                                                        \
    } while (0)
    #define FILL_V(T) do {                                                       \
        int k0t = q0 + (T) * 64;                                                 \
        _Pragma("unroll")                                                        \
        for (int i = 0; i < 8; i++) {                                            \
            int idx = tid + i * 128;                                             \
            int d = idx >> 4, j = idx & 15;                                      \
            cp16(vtb + (d * 64 + ((4 * j) ^ ((d & 1) << 4))) * 4,                \
                 Vb + (size_t)d * SS + k0t + 4 * j);                             \
        }                                                                        \
    } while (0)

    FILL_DK(0); cp_commit();
    FILL_V(0);  cp_commit();

    for (int t = 0; t < nT; t++) {
        int k0 = q0 + t * 64;
        cp_wait<1>();          // Dk(t) resident
        __syncthreads();

        const uint32_t* Dk = sm + DK0;
        const uint32_t* Vp = sm + VT0;
        uint32_t* Pw = sm + PS0;

        // ---- QK: S[16q x 64k] per warp, 3xBF16 over d=64 (all LDS.128) ----
        float s4[8][4] = {};
        #pragma unroll
        for (int K = 0; K < 4; K++) {
            #pragma unroll
            for (int nt = 0; nt < 8; nt++) {
                const uint32_t* br = Dk + (nt * 8 + l4) * 64;
                uint4 Dq = *(const uint4*)&br[(16 * K + 4 * la3) ^ sw];
                mma16(s4[nt], aH[K][0], aH[K][1], aH[K][2], aH[K][3], Dq.x, Dq.z);
                mma16(s4[nt], aH[K][0], aH[K][1], aH[K][2], aH[K][3], Dq.y, Dq.w);
                mma16(s4[nt], aL[K][0], aL[K][1], aL[K][2], aL[K][3], Dq.x, Dq.z);
            }
        }

        __syncthreads();                       // all warps done reading Dk
        if (t + 1 < nT) FILL_DK(t + 1);        // overlaps mask + PV
        cp_commit();

        // ---- mask (k > q strictly) + exp -> Ps (PHI layout, STS.128) ----
        #pragma unroll
        for (int kt2 = 0; kt2 < 4; kt2++) {
            int nt0 = 2 * kt2, nt1 = nt0 + 1;
            int kg0 = k0 + nt0 * 8 + 2 * la3;
            int kg1 = k0 + nt1 * 8 + 2 * la3;
            int qa = q0 + qrow, qb8 = qa + 8;
            float e0 = (kg0     > qa) ? __expf(-0.5f * s4[nt0][0]) : 0.0f;
            float e1 = (kg0 + 1 > qa) ? __expf(-0.5f * s4[nt0][1]) : 0.0f;
            float e2 = (kg1     > qa) ? __expf(-0.5f * s4[nt1][0]) : 0.0f;
            float e3 = (kg1 + 1 > qa) ? __expf(-0.5f * s4[nt1][1]) : 0.0f;
            *(uint4*)&Pw[qrow * 64 + ((16 * kt2 + 4 * la3) ^ sw)] =
                make_uint4(f2tf32(e0), f2tf32(e1), f2tf32(e2), f2tf32(e3));
            e0 = (kg0     > qb8) ? __expf(-0.5f * s4[nt0][2]) : 0.0f;
            e1 = (kg0 + 1 > qb8) ? __expf(-0.5f * s4[nt0][3]) : 0.0f;
            e2 = (kg1     > qb8) ? __expf(-0.5f * s4[nt1][2]) : 0.0f;
            e3 = (kg1 + 1 > qb8) ? __expf(-0.5f * s4[nt1][3]) : 0.0f;
            *(uint4*)&Pw[(qrow + 8) * 64 + ((16 * kt2 + 4 * la3) ^ sw)] =
                make_uint4(f2tf32(e0), f2tf32(e1), f2tf32(e2), f2tf32(e3));
        }
        __syncwarp();   // Pw rows are warp-private

        cp_wait<1>();          // V(t) resident
        __syncthreads();

        // ---- PV: ctx += P @ V over 64 keys (all LDS.128) ----
        #pragma unroll
        for (int kt2 = 0; kt2 < 4; kt2++) {
            uint4 Pa = *(const uint4*)&Pw[qrow * 64 + ((16 * kt2 + 4 * la3) ^ sw)];
            uint4 Pb = *(const uint4*)&Pw[(qrow + 8) * 64 + ((16 * kt2 + 4 * la3) ^ sw)];
            #pragma unroll
            for (int nt = 0; nt < 8; nt++) {
                int vr = nt * 8 + l4;
                uint4 Vq = *(const uint4*)&Vp[vr * 64 + ((16 * kt2 + 4 * la3) ^ ((vr & 1) << 4))];
                mma8(ctx[nt], Pa.x, Pb.x, Pa.y, Pb.y, Vq.x, Vq.y);
                mma8(ctx[nt], Pa.z, Pb.z, Pa.w, Pb.w, Vq.z, Vq.w);
            }
        }

        __syncthreads();                       // all warps done reading Vp/Ps
        if (t + 1 < nT) FILL_V(t + 1);         // overlaps next QK
        cp_commit();
    }

    // Store ctx as tf32 in merged [B,S,H] layout
    uint32_t* Cb = C + (size_t)b * SS * HH + h * HD;
    #pragma unroll
    for (int nt = 0; nt < 8; nt++) {
        int r = q0 + qrow;
        int c = nt * 8 + 2 * la3;
        *(uint2*)&Cb[(size_t)r       * HH + c] = make_uint2(f2tf32(ctx[nt][0]), f2tf32(ctx[nt][1]));
        *(uint2*)&Cb[(size_t)(r + 8) * HH + c] = make_uint2(f2tf32(ctx[nt][2]), f2tf32(ctx[nt][3]));
    }
    #undef FILL_DK
    #undef FILL_V
}

static const int ATTN_SMEM = (3 * 64 * 64) * 4;   // 49152 B
static const int BF3_SMEM  = (2 * 2 * 128 * 32) * 4;  // 65536 B

extern "C" void kernel_launch(void* const* d_in, const int* in_sizes, int n_in,
                              void* d_out, int out_size) {
    const float* x  = (const float*)d_in[0];
    const float* Wq = (const float*)d_in[1];
    const float* bq = (const float*)d_in[2];
    const float* Wk = (const float*)d_in[3];
    const float* bk = (const float*)d_in[4];
    const float* Wv = (const float*)d_in[5];
    const float* bv = (const float*)d_in[6];
    const float* Wo = (const float*)d_in[7];
    const float* bo = (const float*)d_in[8];
    float* out = (float*)d_out;

    uint32_t *pxTF, *pxHL, *pWdT, *pWvTF, *pWoTF, *pDHL, *pVtP, *pC;
    float *pbd;
    cudaGetSymbolAddress((void**)&pxTF,  g_xTF);
    cudaGetSymbolAddress((void**)&pxHL,  g_xHL);
    cudaGetSymbolAddress((void**)&pWdT,  g_WdT);
    cudaGetSymbolAddress((void**)&pWvTF, g_WvTF);
    cudaGetSymbolAddress((void**)&pWoTF, g_WoTF);
    cudaGetSymbolAddress((void**)&pbd,   g_bd);
    cudaGetSymbolAddress((void**)&pDHL,  g_DHL);
    cudaGetSymbolAddress((void**)&pVtP,  g_VtP);
    cudaGetSymbolAddress((void**)&pC,    g_C);

    static bool attr_set = false;
    if (!attr_set) {
        cudaFuncSetAttribute(attn_tc, cudaFuncAttributeMaxDynamicSharedMemorySize, ATTN_SMEM);
        cudaFuncSetAttribute(gemm_bf3, cudaFuncAttributeMaxDynamicSharedMemorySize, BF3_SMEM);
        attr_set = true;
    }

    // 1. prep
    prep_x  <<<(MM * HH / 4) / 256, 256>>>(x, bq, bk);
    prep_wdT<<<dim3(32, 32), 256>>>(Wq, Wk);
    prep_tf2<<<dim3((HH * HH / 4) / 256, 2), 256>>>(Wv, pWvTF, Wo, pWoTF);

    // 2. D = x @ Wd + bd (3xBF16, all-LDS.128) ; V = x @ Wv + bv (tf32)
    dim3 ggrid(HH / 128, MM / 128);
    gemm_bf3<<<ggrid, 256, BF3_SMEM>>>(pxHL, pWdT, pbd, pDHL);
    gemm_tc<3><<<ggrid, 256>>>(pxTF, pWvTF, bv, pVtP);

    // 3. fused attention (LPT: qb slowest-varying, longest first)
    dim3 agrid(NH, BB, SS / 64);
    attn_tc<<<agrid, 128, ATTN_SMEM>>>(pDHL, pVtP, pC);

    // 4. out = ctx @ Wo + bo (tf32)
    gemm_tc<0><<<ggrid, 256>>>(pC, pWoTF, bo, out);
}